// round 7
// baseline (speedup 1.0000x reference)
#include <cuda_runtime.h>
#include <math.h>
#include <stdint.h>

// ---------------------------------------------------------------------------
// Shapes
// ---------------------------------------------------------------------------
#define BATCH 8
#define EMB   768
#define NTOK  784
#define NPI   196
#define NHEAD 12
#define HD    64
#define HID   3072

// ---------------------------------------------------------------------------
// Scratch (device globals — no allocation allowed)
// ---------------------------------------------------------------------------
__device__ float g_X [BATCH * NTOK * EMB];
__device__ float g_H [BATCH * NTOK * EMB];
__device__ float g_FF[BATCH * NTOK * HID];
__device__ float g_pool[BATCH * EMB];
__device__ float g_h1 [BATCH * EMB];
__device__ float g_pt [BATCH * 256];
// tf32-rounded weights (pe_w | qkv_w | proj_w | fc1_w | fc2_w)
#define OFF_PE   0
#define OFF_QKV  2359296
#define OFF_PROJ 7667712
#define OFF_FC1  9437184
#define OFF_FC2  16515072
#define W_TOTAL  23592960
__device__ float g_W[W_TOTAL];

__device__ __forceinline__ float gelu_f(float x) {
    return 0.5f * x * (1.0f + erff(x * 0.7071067811865475f));
}
__device__ __forceinline__ float tf32r(float f) {
    uint32_t u;
    asm("cvt.rna.tf32.f32 %0, %1;" : "=r"(u) : "f"(f));
    return __uint_as_float(u);
}
__device__ __forceinline__ uint32_t sptr(const void* p) {
    return (uint32_t)__cvta_generic_to_shared(p);
}
__device__ __forceinline__ void cp16(uint32_t dst, const void* src, int sz) {
    asm volatile("cp.async.cg.shared.global [%0], [%1], 16, %2;"
                 :: "r"(dst), "l"(src), "r"(sz));
}
__device__ __forceinline__ void mma_tf32(float* d, const uint32_t* a,
                                         uint32_t b0, uint32_t b1) {
    asm volatile(
        "mma.sync.aligned.m16n8k8.row.col.f32.tf32.tf32.f32 "
        "{%0,%1,%2,%3}, {%4,%5,%6,%7}, {%8,%9}, {%0,%1,%2,%3};"
        : "+f"(d[0]), "+f"(d[1]), "+f"(d[2]), "+f"(d[3])
        : "r"(a[0]), "r"(a[1]), "r"(a[2]), "r"(a[3]), "r"(b0), "r"(b1));
}

// ---------------------------------------------------------------------------
// Weight pre-convert (fp32 -> RN tf32), one launch, segmented.
// ---------------------------------------------------------------------------
__global__ void cvt_all_kernel(const float4* __restrict__ s0, const float4* __restrict__ s1,
                               const float4* __restrict__ s2, const float4* __restrict__ s3,
                               const float4* __restrict__ s4, float4* __restrict__ dst)
{
    const int b0 = OFF_QKV / 4, b1 = OFF_PROJ / 4, b2 = OFF_FC1 / 4,
              b3 = OFF_FC2 / 4, b4 = W_TOTAL / 4;
    int i = blockIdx.x * blockDim.x + threadIdx.x;
    int stride = gridDim.x * blockDim.x;
    for (; i < b4; i += stride) {
        const float4* src;
        int off;
        if      (i < b0) { src = s0; off = i; }
        else if (i < b1) { src = s1; off = i - b0; }
        else if (i < b2) { src = s2; off = i - b1; }
        else if (i < b3) { src = s3; off = i - b2; }
        else             { src = s4; off = i - b3; }
        float4 v = src[off];
        v.x = tf32r(v.x); v.y = tf32r(v.y); v.z = tf32r(v.z); v.w = tf32r(v.w);
        dst[i] = v;
    }
}

// ---------------------------------------------------------------------------
// TF32 tensor-core GEMM, cp.async double-buffered, 64x64 warp tiles.
// ---------------------------------------------------------------------------
template<int BM, int BN, int WR, int WC, bool TRANSB, bool GELU, bool ROUND>
__global__ __launch_bounds__(WR*WC*32)
void mma_gemm(const float* __restrict__ A, int lda, long long sA1, long long sA2,
              const float* __restrict__ Bm, int ldb, long long sB1, long long sB2,
              float* __restrict__ C, int ldc, long long sC1, long long sC2,
              const float* __restrict__ bias,
              const float* __restrict__ res, long long sRes,
              int M, int N, int K, int nb2, float scale)
{
    constexpr int BK      = 32;
    constexpr int THREADS = WR * WC * 32;
    constexpr int WTM     = BM / WR;
    constexpr int WTN     = BN / WC;
    constexpr int MT      = WTM / 16;
    constexpr int NT      = WTN / 8;
    constexpr int LK      = BK + 4;
    constexpr int LN      = BN + 8;
    constexpr int ASZ     = BM * LK;
    constexpr int BSZ     = TRANSB ? BN * LK : BK * LN;

    extern __shared__ float smem[];
    float* As = smem;
    float* Bs = smem + 2 * ASZ;

    const int z  = blockIdx.z;
    const int z1 = z / nb2;
    const int z2 = z - z1 * nb2;
    const float* Ab = A  + (long long)z1 * sA1 + (long long)z2 * sA2;
    const float* Bb = Bm + (long long)z1 * sB1 + (long long)z2 * sB2;
    float*       Cb = C  + (long long)z1 * sC1 + (long long)z2 * sC2;

    const int tid  = threadIdx.x;
    const int lane = tid & 31;
    const int warp = tid >> 5;
    const int wm   = warp / WC;
    const int wn   = warp % WC;
    const int m0   = blockIdx.x * BM;
    const int n0   = blockIdx.y * BN;
    const int r    = lane >> 2;
    const int cq   = lane & 3;

    float acc[MT][NT][4];
    #pragma unroll
    for (int i = 0; i < MT; i++)
        #pragma unroll
        for (int j = 0; j < NT; j++)
            #pragma unroll
            for (int q = 0; q < 4; q++) acc[i][j][q] = 0.f;

    auto stage = [&](int buf, int k0) {
        float* Ad = As + buf * ASZ;
        #pragma unroll
        for (int i = 0; i < (BM*(BK/4))/THREADS; i++) {
            int cid = tid + i * THREADS;
            int m   = cid >> 3;
            int k4  = (cid & 7) << 2;
            int gm  = m0 + m, gk = k0 + k4;
            int sz  = (gm < M && gk < K) ? 16 : 0;
            cp16(sptr(&Ad[m * LK + k4]), Ab + (long long)gm * lda + gk, sz);
        }
        float* Bd = Bs + buf * BSZ;
        if (TRANSB) {
            #pragma unroll
            for (int i = 0; i < (BN*(BK/4))/THREADS; i++) {
                int cid = tid + i * THREADS;
                int n   = cid >> 3;
                int k4  = (cid & 7) << 2;
                int gn  = n0 + n, gk = k0 + k4;
                int sz  = (gn < N && gk < K) ? 16 : 0;
                cp16(sptr(&Bd[n * LK + k4]), Bb + (long long)gn * ldb + gk, sz);
            }
        } else {
            constexpr int NB4 = BN / 4;
            #pragma unroll
            for (int i = 0; i < (BK*(BN/4))/THREADS; i++) {
                int cid = tid + i * THREADS;
                int kk  = cid / NB4;
                int n4  = (cid - kk * NB4) * 4;
                int gk  = k0 + kk, gn = n0 + n4;
                int sz  = (gk < K && gn < N) ? 16 : 0;
                cp16(sptr(&Bd[kk * LN + n4]), Bb + (long long)gk * ldb + gn, sz);
            }
        }
    };

    const int nk = (K + BK - 1) / BK;
    stage(0, 0);
    asm volatile("cp.async.commit_group;");

    for (int t = 0; t < nk; t++) {
        asm volatile("cp.async.wait_group 0;");
        __syncthreads();
        if (t + 1 < nk) {
            stage((t + 1) & 1, (t + 1) * BK);
            asm volatile("cp.async.commit_group;");
        }
        const float* Ac = As + (t & 1) * ASZ;
        const float* Bc = Bs + (t & 1) * BSZ;

        #pragma unroll
        for (int kk = 0; kk < BK; kk += 8) {
            uint32_t af[MT][4];
            uint32_t bf[NT][2];
            #pragma unroll
            for (int mt = 0; mt < MT; mt++) {
                int row = wm * WTM + mt * 16 + r;
                af[mt][0] = __float_as_uint(Ac[row       * LK + kk + cq]);
                af[mt][1] = __float_as_uint(Ac[(row + 8) * LK + kk + cq]);
                af[mt][2] = __float_as_uint(Ac[row       * LK + kk + cq + 4]);
                af[mt][3] = __float_as_uint(Ac[(row + 8) * LK + kk + cq + 4]);
            }
            #pragma unroll
            for (int nt = 0; nt < NT; nt++) {
                int col = wn * WTN + nt * 8 + r;
                if (TRANSB) {
                    bf[nt][0] = __float_as_uint(Bc[col * LK + kk + cq]);
                    bf[nt][1] = __float_as_uint(Bc[col * LK + kk + cq + 4]);
                } else {
                    bf[nt][0] = __float_as_uint(Bc[(kk + cq)     * LN + col]);
                    bf[nt][1] = __float_as_uint(Bc[(kk + cq + 4) * LN + col]);
                }
            }
            #pragma unroll
            for (int mt = 0; mt < MT; mt++)
                #pragma unroll
                for (int nt = 0; nt < NT; nt++)
                    mma_tf32(acc[mt][nt], af[mt], bf[nt][0], bf[nt][1]);
        }
        __syncthreads();
    }

    // epilogue: float2-vectorized (n pairs are contiguous; N % BN == 0 here)
    #pragma unroll
    for (int mt = 0; mt < MT; mt++) {
        #pragma unroll
        for (int i = 0; i < 2; i++) {
            int gm = m0 + wm * WTM + mt * 16 + r + i * 8;
            if (gm >= M) continue;
            #pragma unroll
            for (int nt = 0; nt < NT; nt++) {
                int gn = n0 + wn * WTN + nt * 8 + cq * 2;
                if (gn + 1 >= N) continue;
                float v0 = acc[mt][nt][i * 2 + 0] * scale;
                float v1 = acc[mt][nt][i * 2 + 1] * scale;
                if (bias) {
                    float2 bb = *reinterpret_cast<const float2*>(&bias[gn]);
                    v0 += bb.x; v1 += bb.y;
                }
                if (GELU) { v0 = gelu_f(v0); v1 = gelu_f(v1); }
                if (res) {
                    float2 rr = *reinterpret_cast<const float2*>(
                        &res[(long long)z * sRes + (long long)gm * ldc + gn]);
                    v0 += rr.x; v1 += rr.y;
                }
                if (ROUND) { v0 = tf32r(v0); v1 = tf32r(v1); }
                float2 o; o.x = v0; o.y = v1;
                *reinterpret_cast<float2*>(&Cb[(long long)gm * ldc + gn]) = o;
            }
        }
    }
}

// ---------------------------------------------------------------------------
// Flash attention: per (b,h,q-tile 64). 4 warps x 16 q-rows. HD=64.
// ---------------------------------------------------------------------------
#define FLDK 68
#define FLDV 72
#define FQS  0
#define FKS  (64*FLDK)
#define FVS  (FKS + 2*64*FLDK)
#define FPS  (FVS + 2*64*FLDV)
#define FSM_FLOATS (FPS + 4*16*FLDK)
#define FSM_BYTES  (FSM_FLOATS*4)

__global__ __launch_bounds__(128)
void flash_kernel(const float* __restrict__ QKV, float* __restrict__ O, int Ncur)
{
    const int qt  = blockIdx.x;
    const int bh  = blockIdx.y;
    const int b   = bh / NHEAD;
    const int h   = bh % NHEAD;
    const int tid = threadIdx.x;
    const int warp = tid >> 5, lane = tid & 31;
    const int r = lane >> 2, cq = lane & 3;

    extern __shared__ float sm[];
    float* Qs = sm + FQS;
    float* Ks = sm + FKS;
    float* Vs = sm + FVS;
    float* Ps = sm + FPS + warp * 16 * FLDK;

    const float* Qb = QKV + (long long)b * NTOK * 2304 + h * 64;
    const float* Kb = Qb + 768;
    const int q0 = qt * 64;

    for (int i = tid; i < 64 * 16; i += 128) {
        int row = i >> 4, k4 = (i & 15) << 2;
        int gq = q0 + row;
        cp16(sptr(&Qs[row * FLDK + k4]), Qb + (long long)gq * 2304 + k4,
             gq < Ncur ? 16 : 0);
    }
    auto stageKV = [&](int buf, int j0) {
        float* Kd = Ks + buf * 64 * FLDK;
        float* Vd = Vs + buf * 64 * FLDV;
        for (int i = tid; i < 64 * 16; i += 128) {
            int row = i >> 4, k4 = (i & 15) << 2;
            int gj = j0 + row;
            int sz = gj < Ncur ? 16 : 0;
            const float* src = Kb + (long long)gj * 2304 + k4;
            cp16(sptr(&Kd[row * FLDK + k4]), src, sz);
            cp16(sptr(&Vd[row * FLDV + k4]), src + 768, sz);
        }
    };

    const int nj = (Ncur + 63) >> 6;
    stageKV(0, 0);
    asm volatile("cp.async.commit_group;");
    asm volatile("cp.async.wait_group 0;");
    __syncthreads();

    uint32_t qf[8][4];
    {
        int row = warp * 16 + r;
        #pragma unroll
        for (int ks = 0; ks < 8; ks++) {
            qf[ks][0] = __float_as_uint(Qs[row       * FLDK + ks * 8 + cq]);
            qf[ks][1] = __float_as_uint(Qs[(row + 8) * FLDK + ks * 8 + cq]);
            qf[ks][2] = __float_as_uint(Qs[row       * FLDK + ks * 8 + cq + 4]);
            qf[ks][3] = __float_as_uint(Qs[(row + 8) * FLDK + ks * 8 + cq + 4]);
        }
    }

    float oacc[8][4];
    #pragma unroll
    for (int i = 0; i < 8; i++)
        #pragma unroll
        for (int q = 0; q < 4; q++) oacc[i][q] = 0.f;
    float mrow[2] = {-1e30f, -1e30f};
    float lrow[2] = {0.f, 0.f};

    for (int j = 0; j < nj; j++) {
        if (j + 1 < nj) {
            stageKV((j + 1) & 1, (j + 1) * 64);
            asm volatile("cp.async.commit_group;");
        }
        const float* Kc = Ks + (j & 1) * 64 * FLDK;
        const float* Vc = Vs + (j & 1) * 64 * FLDV;

        float sacc[8][4];
        #pragma unroll
        for (int i = 0; i < 8; i++)
            #pragma unroll
            for (int q = 0; q < 4; q++) sacc[i][q] = 0.f;
        #pragma unroll
        for (int ks = 0; ks < 8; ks++) {
            #pragma unroll
            for (int nt = 0; nt < 8; nt++) {
                int col = nt * 8 + r;
                uint32_t b0 = __float_as_uint(Kc[col * FLDK + ks * 8 + cq]);
                uint32_t b1 = __float_as_uint(Kc[col * FLDK + ks * 8 + cq + 4]);
                mma_tf32(sacc[nt], qf[ks], b0, b1);
            }
        }

        const int j0 = j * 64;
        float rmax[2] = {-1e30f, -1e30f};
        #pragma unroll
        for (int nt = 0; nt < 8; nt++) {
            #pragma unroll
            for (int q = 0; q < 4; q++) {
                int col = j0 + nt * 8 + cq * 2 + (q & 1);
                float v = (col < Ncur) ? sacc[nt][q] * 0.125f : -1e30f;
                sacc[nt][q] = v;
                rmax[q >> 1] = fmaxf(rmax[q >> 1], v);
            }
        }
        #pragma unroll
        for (int i = 0; i < 2; i++) {
            rmax[i] = fmaxf(rmax[i], __shfl_xor_sync(0xffffffffu, rmax[i], 1));
            rmax[i] = fmaxf(rmax[i], __shfl_xor_sync(0xffffffffu, rmax[i], 2));
        }
        float alpha[2];
        #pragma unroll
        for (int i = 0; i < 2; i++) {
            float mnew = fmaxf(mrow[i], rmax[i]);
            alpha[i] = expf(mrow[i] - mnew);
            mrow[i] = mnew;
        }
        float rsum[2] = {0.f, 0.f};
        #pragma unroll
        for (int nt = 0; nt < 8; nt++)
            #pragma unroll
            for (int q = 0; q < 4; q++) {
                float e = expf(sacc[nt][q] - mrow[q >> 1]);
                sacc[nt][q] = e;
                rsum[q >> 1] += e;
            }
        #pragma unroll
        for (int i = 0; i < 2; i++) {
            rsum[i] += __shfl_xor_sync(0xffffffffu, rsum[i], 1);
            rsum[i] += __shfl_xor_sync(0xffffffffu, rsum[i], 2);
            lrow[i] = lrow[i] * alpha[i] + rsum[i];
        }
        #pragma unroll
        for (int nt = 0; nt < 8; nt++)
            #pragma unroll
            for (int q = 0; q < 4; q++)
                oacc[nt][q] *= alpha[q >> 1];

        #pragma unroll
        for (int nt = 0; nt < 8; nt++) {
            Ps[r       * FLDK + nt * 8 + cq * 2]     = tf32r(sacc[nt][0]);
            Ps[r       * FLDK + nt * 8 + cq * 2 + 1] = tf32r(sacc[nt][1]);
            Ps[(r + 8) * FLDK + nt * 8 + cq * 2]     = tf32r(sacc[nt][2]);
            Ps[(r + 8) * FLDK + nt * 8 + cq * 2 + 1] = tf32r(sacc[nt][3]);
        }
        __syncwarp();
        #pragma unroll
        for (int ks = 0; ks < 8; ks++) {
            uint32_t af[4];
            af[0] = __float_as_uint(Ps[r       * FLDK + ks * 8 + cq]);
            af[1] = __float_as_uint(Ps[(r + 8) * FLDK + ks * 8 + cq]);
            af[2] = __float_as_uint(Ps[r       * FLDK + ks * 8 + cq + 4]);
            af[3] = __float_as_uint(Ps[(r + 8) * FLDK + ks * 8 + cq + 4]);
            #pragma unroll
            for (int nt = 0; nt < 8; nt++) {
                uint32_t b0 = __float_as_uint(Vc[(ks * 8 + cq)     * FLDV + nt * 8 + r]);
                uint32_t b1 = __float_as_uint(Vc[(ks * 8 + cq + 4) * FLDV + nt * 8 + r]);
                mma_tf32(oacc[nt], af, b0, b1);
            }
        }
        __syncwarp();
        if (j + 1 < nj) asm volatile("cp.async.wait_group 0;");
        __syncthreads();
    }

    float inv0 = 1.f / lrow[0], inv1 = 1.f / lrow[1];
    int row0 = q0 + warp * 16 + r;
    #pragma unroll
    for (int nt = 0; nt < 8; nt++) {
        int col = h * 64 + nt * 8 + cq * 2;
        if (row0 < Ncur) {
            float2 o; o.x = tf32r(oacc[nt][0] * inv0); o.y = tf32r(oacc[nt][1] * inv0);
            *reinterpret_cast<float2*>(O + ((long long)b * NTOK + row0) * EMB + col) = o;
        }
        if (row0 + 8 < Ncur) {
            float2 o; o.x = tf32r(oacc[nt][2] * inv1); o.y = tf32r(oacc[nt][3] * inv1);
            *reinterpret_cast<float2*>(O + ((long long)b * NTOK + row0 + 8) * EMB + col) = o;
        }
    }
}

// ---------------------------------------------------------------------------
// LayerNorm over EMB=768 (optionally tf32-round output). Safe for src==dst.
// ---------------------------------------------------------------------------
__global__ void ln_kernel(const float* __restrict__ src, float* __restrict__ dst,
                          const float* __restrict__ g, const float* __restrict__ bb,
                          int roundOut)
{
    long long row = (long long)blockIdx.y * NTOK + blockIdx.x;
    const float* x = src + row * EMB;
    float*       o = dst + row * EMB;
    int t = threadIdx.x;
    __shared__ float sh[8];

    float v0 = x[t], v1 = x[t + 256], v2 = x[t + 512];
    float s = v0 + v1 + v2;
    #pragma unroll
    for (int off = 16; off; off >>= 1) s += __shfl_xor_sync(0xffffffffu, s, off);
    if ((t & 31) == 0) sh[t >> 5] = s;
    __syncthreads();
    float tot = 0.f;
    #pragma unroll
    for (int i = 0; i < 8; i++) tot += sh[i];
    float mu = tot * (1.f / 768.f);

    float d0 = v0 - mu, d1 = v1 - mu, d2 = v2 - mu;
    float q = d0*d0 + d1*d1 + d2*d2;
    #pragma unroll
    for (int off = 16; off; off >>= 1) q += __shfl_xor_sync(0xffffffffu, q, off);
    __syncthreads();
    if ((t & 31) == 0) sh[t >> 5] = q;
    __syncthreads();
    float vt = 0.f;
    #pragma unroll
    for (int i = 0; i < 8; i++) vt += sh[i];
    float inv = rsqrtf(vt * (1.f / 768.f) + 1e-5f);

    float o0 = d0 * inv * g[t]       + bb[t];
    float o1 = d1 * inv * g[t + 256] + bb[t + 256];
    float o2 = d2 * inv * g[t + 512] + bb[t + 512];
    if (roundOut) { o0 = tf32r(o0); o1 = tf32r(o1); o2 = tf32r(o2); }
    o[t] = o0; o[t + 256] = o1; o[t + 512] = o2;
}

// ---------------------------------------------------------------------------
// im2col (tf32-rounded: feeds patch-embed mma A operand)
// ---------------------------------------------------------------------------
__global__ void im2col_kernel(const float* __restrict__ img, float* __restrict__ dst, int imgIdx)
{
    int idx = blockIdx.x * 256 + threadIdx.x;
    if (idx >= BATCH * NPI * EMB) return;
    int k = idx % EMB;
    int p = (idx / EMB) % NPI;
    int b = idx / (EMB * NPI);
    int c  = k / 256;
    int pr = (k / 16) & 15;
    int pc = k & 15;
    int gr = p / 14, gc = p % 14;
    float v = img[(((long long)b * 3 + c) * 224 + gr * 16 + pr) * 224 + gc * 16 + pc];
    dst[((long long)b * NTOK + imgIdx * NPI + p) * EMB + k] = tf32r(v);
}

__global__ void posadd_kernel(float* __restrict__ X, const float* __restrict__ sp,
                              const float* __restrict__ ip)
{
    int idx = blockIdx.x * 256 + threadIdx.x;
    if (idx >= BATCH * NTOK * EMB) return;
    int e = idx % EMB;
    int n = (idx / EMB) % NTOK;
    float add = (e < 384) ? sp[(n % NPI) * 384 + e]
                          : ip[(n / NPI) * 384 + (e - 384)];
    X[idx] += add;
}

__global__ void small_gemm(const float* __restrict__ A, const float* __restrict__ W,
                           const float* __restrict__ bias, float* __restrict__ C,
                           int M, int N, int K, int gelu)
{
    int gt   = blockIdx.x * blockDim.x + threadIdx.x;
    int warp = gt >> 5, lane = gt & 31;
    if (warp >= M * N) return;
    int m = warp / N, n = warp % N;
    float s = 0.f;
    for (int k = lane; k < K; k += 32) s += A[m * K + k] * W[(long long)n * K + k];
    #pragma unroll
    for (int o = 16; o; o >>= 1) s += __shfl_xor_sync(0xffffffffu, s, o);
    if (lane == 0) {
        s += bias[n];
        if (gelu) s = gelu_f(s);
        C[m * N + n] = s;
    }
}

__global__ void mean_kernel(const float* __restrict__ H, float* __restrict__ pool)
{
    int b = blockIdx.x, e = threadIdx.x;
    float s = 0.f;
    for (int n = 0; n < NTOK; n++) s += H[((long long)b * NTOK + n) * EMB + e];
    pool[b * EMB + e] = s * (1.0f / (float)NTOK);
}

__global__ void expand_kernel(const float* __restrict__ pt, float* __restrict__ out)
{
    int idx = blockIdx.x * 256 + threadIdx.x;
    if (idx >= BATCH * 224 * 224) return;
    int c = idx % 224;
    int r = (idx / 224) % 224;
    int b = idx / (224 * 224);
    out[idx] = pt[b * 256 + (r & 15) * 16 + (c & 15)];
}

// ---------------------------------------------------------------------------
// Host orchestration
// ---------------------------------------------------------------------------
extern "C" void kernel_launch(void* const* d_in, const int* in_sizes, int n_in,
                              void* d_out, int out_size)
{
    const float* img[4];
    for (int i = 0; i < 4; i++) img[i] = (const float*)d_in[i];
    const float* pe_w      = (const float*)d_in[4];
    const float* pe_b      = (const float*)d_in[5];
    const float* sp        = (const float*)d_in[6];
    const float* ip        = (const float*)d_in[7];
    const float* ln_attn_g = (const float*)d_in[8];
    const float* ln_attn_b = (const float*)d_in[9];
    const float* qkv_w     = (const float*)d_in[10];
    const float* qkv_b     = (const float*)d_in[11];
    const float* proj_w    = (const float*)d_in[12];
    const float* proj_b    = (const float*)d_in[13];
    const float* ln1_g     = (const float*)d_in[14];
    const float* ln1_b     = (const float*)d_in[15];
    const float* fc1_w     = (const float*)d_in[16];
    const float* fc1_b     = (const float*)d_in[17];
    const float* fc2_w     = (const float*)d_in[18];
    const float* fc2_b     = (const float*)d_in[19];
    const float* ln2_g     = (const float*)d_in[20];
    const float* ln2_b     = (const float*)d_in[21];
    const float* final_g   = (const float*)d_in[22];
    const float* final_b   = (const float*)d_in[23];
    const float* head_w1   = (const float*)d_in[24];
    const float* head_b1   = (const float*)d_in[25];
    const float* head_w2   = (const float*)d_in[26];
    const float* head_b2   = (const float*)d_in[27];
    float* out = (float*)d_out;

    float *X, *H, *FF, *pool, *h1, *pt, *W;
    cudaGetSymbolAddress((void**)&X,    g_X);
    cudaGetSymbolAddress((void**)&H,    g_H);
    cudaGetSymbolAddress((void**)&FF,   g_FF);
    cudaGetSymbolAddress((void**)&pool, g_pool);
    cudaGetSymbolAddress((void**)&h1,   g_h1);
    cudaGetSymbolAddress((void**)&pt,   g_pt);
    cudaGetSymbolAddress((void**)&W,    g_W);

    const int SMEM_W = (2*128*36 + 2*128*36) * 4;   // 73728
    cudaFuncSetAttribute(mma_gemm<128,128,2,2,true,false,false>,
                         cudaFuncAttributeMaxDynamicSharedMemorySize, SMEM_W);
    cudaFuncSetAttribute(mma_gemm<128,128,2,2,true,false,true>,
                         cudaFuncAttributeMaxDynamicSharedMemorySize, SMEM_W);
    cudaFuncSetAttribute(mma_gemm<128,128,2,2,true,true,true>,
                         cudaFuncAttributeMaxDynamicSharedMemorySize, SMEM_W);
    cudaFuncSetAttribute(flash_kernel,
                         cudaFuncAttributeMaxDynamicSharedMemorySize, FSM_BYTES);

    const long long SXE = (long long)NTOK * EMB;
    const long long SXQ = (long long)NTOK * 2304;
    const long long SXF = (long long)NTOK * HID;

    // ---- pre-convert all weights to RN tf32 (single launch) ----
    cvt_all_kernel<<<1024, 256>>>((const float4*)pe_w, (const float4*)qkv_w,
                                  (const float4*)proj_w, (const float4*)fc1_w,
                                  (const float4*)fc2_w, (float4*)W);

    // ---- patch embed + positional encode ----
    {
        int total = BATCH * NPI * EMB;
        for (int i = 0; i < 4; i++)
            im2col_kernel<<<(total + 255) / 256, 256>>>(img[i], FF, i);
        for (int i = 0; i < 4; i++) {
            mma_gemm<128,128,2,2,true,false,false><<<dim3(2, 6, BATCH), 128, SMEM_W>>>(
                FF + (long long)i * NPI * EMB, EMB, SXE, 0,
                W + OFF_PE + (long long)i * EMB * EMB, EMB, 0, 0,
                X + (long long)i * NPI * EMB, EMB, SXE, 0,
                pe_b + i * EMB, nullptr, 0,
                NPI, EMB, EMB, 1, 1.f);
        }
        int tot2 = BATCH * NTOK * EMB;
        posadd_kernel<<<(tot2 + 255) / 256, 256>>>(X, sp, ip);
    }

    // ---- transformer blocks ----
    for (int blk = 0; blk < 3; blk++) {
        int Ncur = 392 + 196 * blk;
        int mt128 = (Ncur + 127) / 128;
        int nqt   = (Ncur + 63) / 64;

        ln_kernel<<<dim3(Ncur, BATCH), 256>>>(X, H, ln_attn_g + blk*EMB, ln_attn_b + blk*EMB, 1);

        // QKV (rounded out: feeds flash)
        mma_gemm<128,128,2,2,true,false,true><<<dim3(mt128, 18, BATCH), 128, SMEM_W>>>(
            H, EMB, SXE, 0,
            W + OFF_QKV + (long long)blk * 2304 * EMB, EMB, 0, 0,
            FF, 2304, SXQ, 0,
            qkv_b + blk * 2304, nullptr, 0,
            Ncur, 2304, EMB, 1, 1.f);

        // fused attention -> H
        flash_kernel<<<dim3(nqt, BATCH * NHEAD), 128, FSM_BYTES>>>(FF, H, Ncur);

        // X = X + O @ proj_w^T + proj_b
        mma_gemm<128,128,2,2,true,false,false><<<dim3(mt128, 6, BATCH), 128, SMEM_W>>>(
            H, EMB, SXE, 0,
            W + OFF_PROJ + (long long)blk * EMB * EMB, EMB, 0, 0,
            X, EMB, SXE, 0,
            proj_b + blk * EMB, X, SXE,
            Ncur, EMB, EMB, 1, 1.f);

        ln_kernel<<<dim3(Ncur, BATCH), 256>>>(X, H, ln1_g + blk*EMB, ln1_b + blk*EMB, 1);

        // FF = gelu(H @ fc1_w^T + fc1_b) (rounded out)
        mma_gemm<128,128,2,2,true,true,true><<<dim3(mt128, 24, BATCH), 128, SMEM_W>>>(
            H, EMB, SXE, 0,
            W + OFF_FC1 + (long long)blk * HID * EMB, EMB, 0, 0,
            FF, HID, SXF, 0,
            fc1_b + blk * HID, nullptr, 0,
            Ncur, HID, EMB, 1, 1.f);

        // X = X + FF @ fc2_w^T + fc2_b
        mma_gemm<128,128,2,2,true,false,false><<<dim3(mt128, 6, BATCH), 128, SMEM_W>>>(
            FF, HID, SXF, 0,
            W + OFF_FC2 + (long long)blk * EMB * HID, HID, 0, 0,
            X, EMB, SXE, 0,
            fc2_b + blk * EMB, X, SXE,
            Ncur, EMB, HID, 1, 1.f);

        // LN2 in place (full fp32 state, no rounding)
        ln_kernel<<<dim3(Ncur, BATCH), 256>>>(X, X, ln2_g + blk*EMB, ln2_b + blk*EMB, 0);
    }

    // ---- final LN, mean-pool, head, expand ----
    ln_kernel<<<dim3(NTOK, BATCH), 256>>>(X, H, final_g, final_b, 0);
    mean_kernel<<<BATCH, EMB>>>(H, pool);
    small_gemm<<<(BATCH * EMB * 32 + 255) / 256, 256>>>(pool, head_w1, head_b1, h1,
                                                        BATCH, EMB, EMB, 1);
    small_gemm<<<(BATCH * 256 * 32 + 255) / 256, 256>>>(h1, head_w2, head_b2, pt,
                                                        BATCH, 256, EMB, 0);
    expand_kernel<<<(BATCH * 224 * 224 + 255) / 256, 256>>>(pt, out);
}

// round 12
// speedup vs baseline: 1.1034x; 1.1034x over previous
#include <cuda_runtime.h>
#include <math.h>
#include <stdint.h>

// ---------------------------------------------------------------------------
// Shapes
// ---------------------------------------------------------------------------
#define BATCH 8
#define EMB   768
#define NTOK  784
#define NPI   196
#define NHEAD 12
#define HD    64
#define HID   3072

// ---------------------------------------------------------------------------
// Scratch (device globals — no allocation allowed)
// ---------------------------------------------------------------------------
__device__ float g_X [BATCH * NTOK * EMB];
__device__ float g_H [BATCH * NTOK * EMB];
__device__ float g_FF[BATCH * NTOK * HID];
__device__ float g_pool[BATCH * EMB];
__device__ float g_h1 [BATCH * EMB];
__device__ float g_pt [BATCH * 256];
// tf32-rounded weights (pe_w | qkv_w | proj_w | fc1_w | fc2_w)
#define OFF_PE   0
#define OFF_QKV  2359296
#define OFF_PROJ 7667712
#define OFF_FC1  9437184
#define OFF_FC2  16515072
#define W_TOTAL  23592960
__device__ float g_W[W_TOTAL];

__device__ __forceinline__ float gelu_f(float x) {
    return 0.5f * x * (1.0f + erff(x * 0.7071067811865475f));
}
__device__ __forceinline__ float tf32r(float f) {
    uint32_t u;
    asm("cvt.rna.tf32.f32 %0, %1;" : "=r"(u) : "f"(f));
    return __uint_as_float(u);
}
__device__ __forceinline__ uint32_t sptr(const void* p) {
    return (uint32_t)__cvta_generic_to_shared(p);
}
__device__ __forceinline__ void cp16(uint32_t dst, const void* src, int sz) {
    asm volatile("cp.async.cg.shared.global [%0], [%1], 16, %2;"
                 :: "r"(dst), "l"(src), "r"(sz));
}
__device__ __forceinline__ void mma_tf32(float* d, const uint32_t* a,
                                         uint32_t b0, uint32_t b1) {
    asm volatile(
        "mma.sync.aligned.m16n8k8.row.col.f32.tf32.tf32.f32 "
        "{%0,%1,%2,%3}, {%4,%5,%6,%7}, {%8,%9}, {%0,%1,%2,%3};"
        : "+f"(d[0]), "+f"(d[1]), "+f"(d[2]), "+f"(d[3])
        : "r"(a[0]), "r"(a[1]), "r"(a[2]), "r"(a[3]), "r"(b0), "r"(b1));
}
__device__ __forceinline__ void ldsm4(uint32_t* r, uint32_t addr) {
    asm volatile("ldmatrix.sync.aligned.m8n8.x4.shared.b16 {%0,%1,%2,%3}, [%4];"
                 : "=r"(r[0]), "=r"(r[1]), "=r"(r[2]), "=r"(r[3]) : "r"(addr));
}

// ---------------------------------------------------------------------------
// Weight pre-convert (fp32 -> RN tf32), one launch, segmented.
// ---------------------------------------------------------------------------
__global__ void cvt_all_kernel(const float4* __restrict__ s0, const float4* __restrict__ s1,
                               const float4* __restrict__ s2, const float4* __restrict__ s3,
                               const float4* __restrict__ s4, float4* __restrict__ dst)
{
    const int b0 = OFF_QKV / 4, b1 = OFF_PROJ / 4, b2 = OFF_FC1 / 4,
              b3 = OFF_FC2 / 4, b4 = W_TOTAL / 4;
    int i = blockIdx.x * blockDim.x + threadIdx.x;
    int stride = gridDim.x * blockDim.x;
    for (; i < b4; i += stride) {
        const float4* src;
        int off;
        if      (i < b0) { src = s0; off = i; }
        else if (i < b1) { src = s1; off = i - b0; }
        else if (i < b2) { src = s2; off = i - b1; }
        else if (i < b3) { src = s3; off = i - b2; }
        else             { src = s4; off = i - b3; }
        float4 v = src[off];
        v.x = tf32r(v.x); v.y = tf32r(v.y); v.z = tf32r(v.z); v.w = tf32r(v.w);
        dst[i] = v;
    }
}

// ---------------------------------------------------------------------------
// TF32 tensor-core GEMM: 3-stage cp.async pipeline (1 sync/chunk) + ldmatrix
// fragment loads. B is always row-major-K (TRANSB pattern), tiles [n][LK].
// ---------------------------------------------------------------------------
template<int BM, int BN, int WR, int WC, bool GELU, bool ROUND>
__global__ __launch_bounds__(WR*WC*32)
void mma_gemm(const float* __restrict__ A, int lda, long long sA1,
              const float* __restrict__ Bm, int ldb, long long sB1,
              float* __restrict__ C, int ldc, long long sC1,
              const float* __restrict__ bias,
              const float* __restrict__ res, long long sRes,
              int M, int N, int K, float scale)
{
    constexpr int BK      = 32;
    constexpr int THREADS = WR * WC * 32;
    constexpr int WTM     = BM / WR;
    constexpr int WTN     = BN / WC;
    constexpr int MT      = WTM / 16;
    constexpr int NT      = WTN / 8;
    constexpr int LK      = BK + 4;       // 36 floats: LDSM phases conflict-free
    constexpr int ASZ     = BM * LK;
    constexpr int BSZ     = BN * LK;
    constexpr int STAGES  = 3;

    extern __shared__ float smem[];
    float* As = smem;                      // STAGES * ASZ
    float* Bs = smem + STAGES * ASZ;       // STAGES * BSZ

    const int z = blockIdx.z;
    const float* Ab = A  + (long long)z * sA1;
    const float* Bb = Bm + (long long)z * sB1;
    float*       Cb = C  + (long long)z * sC1;

    const int tid  = threadIdx.x;
    const int lane = tid & 31;
    const int warp = tid >> 5;
    const int wm   = warp / WC;
    const int wn   = warp % WC;
    const int m0   = blockIdx.x * BM;
    const int n0   = blockIdx.y * BN;
    const int r    = lane >> 2;
    const int cq   = lane & 3;

    float acc[MT][NT][4];
    #pragma unroll
    for (int i = 0; i < MT; i++)
        #pragma unroll
        for (int j = 0; j < NT; j++)
            #pragma unroll
            for (int q = 0; q < 4; q++) acc[i][j][q] = 0.f;

    auto stage = [&](int buf, int k0) {
        float* Ad = As + buf * ASZ;
        #pragma unroll
        for (int i = 0; i < (BM*(BK/4))/THREADS; i++) {
            int cid = tid + i * THREADS;
            int m   = cid >> 3;
            int k4  = (cid & 7) << 2;
            int gm  = m0 + m, gk = k0 + k4;
            int sz  = (gm < M && gk < K) ? 16 : 0;
            cp16(sptr(&Ad[m * LK + k4]), Ab + (long long)gm * lda + gk, sz);
        }
        float* Bd = Bs + buf * BSZ;
        #pragma unroll
        for (int i = 0; i < (BN*(BK/4))/THREADS; i++) {
            int cid = tid + i * THREADS;
            int n   = cid >> 3;
            int k4  = (cid & 7) << 2;
            int gn  = n0 + n, gk = k0 + k4;
            int sz  = (gn < N && gk < K) ? 16 : 0;
            cp16(sptr(&Bd[n * LK + k4]), Bb + (long long)gn * ldb + gk, sz);
        }
    };

    const int nk = (K + BK - 1) / BK;
    stage(0, 0);
    asm volatile("cp.async.commit_group;");
    if (nk > 1) stage(1, BK);
    asm volatile("cp.async.commit_group;");

    // LDSM lane addressing (constant across k-steps except kk offset)
    const int a_row = (lane & 15);             // within 16-row tile
    const int a_kc  = (lane >> 4) << 2;        // 0 or 4
    const int b_col = ((lane >> 4) << 3) + (lane & 7);   // within 16-col pair
    const int b_kc  = ((lane >> 3) & 1) << 2;  // 0,4,0,4

    for (int t = 0; t < nk; t++) {
        asm volatile("cp.async.wait_group 1;");
        __syncthreads();
        if (t + 2 < nk) stage((t + 2) % STAGES, (t + 2) * BK);
        asm volatile("cp.async.commit_group;");

        const float* Ac = As + (t % STAGES) * ASZ;
        const float* Bc = Bs + (t % STAGES) * BSZ;

        #pragma unroll
        for (int kk = 0; kk < BK; kk += 8) {
            uint32_t af[MT][4];
            uint32_t bf[NT][2];
            #pragma unroll
            for (int mt = 0; mt < MT; mt++) {
                int row = wm * WTM + mt * 16 + a_row;
                ldsm4(af[mt], sptr(&Ac[row * LK + kk + a_kc]));
            }
            #pragma unroll
            for (int np = 0; np < NT; np += 2) {
                int col = wn * WTN + np * 8 + b_col;
                uint32_t tmp[4];
                ldsm4(tmp, sptr(&Bc[col * LK + kk + b_kc]));
                bf[np][0]     = tmp[0]; bf[np][1]     = tmp[1];
                bf[np + 1][0] = tmp[2]; bf[np + 1][1] = tmp[3];
            }
            #pragma unroll
            for (int mt = 0; mt < MT; mt++)
                #pragma unroll
                for (int nt = 0; nt < NT; nt++)
                    mma_tf32(acc[mt][nt], af[mt], bf[nt][0], bf[nt][1]);
        }
    }
    __syncthreads();

    // epilogue: float2-vectorized (N % BN == 0 for all uses)
    #pragma unroll
    for (int mt = 0; mt < MT; mt++) {
        #pragma unroll
        for (int i = 0; i < 2; i++) {
            int gm = m0 + wm * WTM + mt * 16 + r + i * 8;
            if (gm >= M) continue;
            #pragma unroll
            for (int nt = 0; nt < NT; nt++) {
                int gn = n0 + wn * WTN + nt * 8 + cq * 2;
                if (gn + 1 >= N) continue;
                float v0 = acc[mt][nt][i * 2 + 0] * scale;
                float v1 = acc[mt][nt][i * 2 + 1] * scale;
                if (bias) {
                    float2 bb = *reinterpret_cast<const float2*>(&bias[gn]);
                    v0 += bb.x; v1 += bb.y;
                }
                if (GELU) { v0 = gelu_f(v0); v1 = gelu_f(v1); }
                if (res) {
                    float2 rr = *reinterpret_cast<const float2*>(
                        &res[(long long)z * sRes + (long long)gm * ldc + gn]);
                    v0 += rr.x; v1 += rr.y;
                }
                if (ROUND) { v0 = tf32r(v0); v1 = tf32r(v1); }
                float2 o; o.x = v0; o.y = v1;
                *reinterpret_cast<float2*>(&Cb[(long long)gm * ldc + gn]) = o;
            }
        }
    }
}

// ---------------------------------------------------------------------------
// Flash attention: per (b,h,q-tile 64). 4 warps x 16 q-rows. HD=64.
// ---------------------------------------------------------------------------
#define FLDK 68
#define FLDV 72
#define FQS  0
#define FKS  (64*FLDK)
#define FVS  (FKS + 2*64*FLDK)
#define FPS  (FVS + 2*64*FLDV)
#define FSM_FLOATS (FPS + 4*16*FLDK)
#define FSM_BYTES  (FSM_FLOATS*4)

__global__ __launch_bounds__(128)
void flash_kernel(const float* __restrict__ QKV, float* __restrict__ O, int Ncur)
{
    const int qt  = blockIdx.x;
    const int bh  = blockIdx.y;
    const int b   = bh / NHEAD;
    const int h   = bh % NHEAD;
    const int tid = threadIdx.x;
    const int warp = tid >> 5, lane = tid & 31;
    const int r = lane >> 2, cq = lane & 3;

    extern __shared__ float sm[];
    float* Qs = sm + FQS;
    float* Ks = sm + FKS;
    float* Vs = sm + FVS;
    float* Ps = sm + FPS + warp * 16 * FLDK;

    const float* Qb = QKV + (long long)b * NTOK * 2304 + h * 64;
    const float* Kb = Qb + 768;
    const int q0 = qt * 64;

    for (int i = tid; i < 64 * 16; i += 128) {
        int row = i >> 4, k4 = (i & 15) << 2;
        int gq = q0 + row;
        cp16(sptr(&Qs[row * FLDK + k4]), Qb + (long long)gq * 2304 + k4,
             gq < Ncur ? 16 : 0);
    }
    auto stageKV = [&](int buf, int j0) {
        float* Kd = Ks + buf * 64 * FLDK;
        float* Vd = Vs + buf * 64 * FLDV;
        for (int i = tid; i < 64 * 16; i += 128) {
            int row = i >> 4, k4 = (i & 15) << 2;
            int gj = j0 + row;
            int sz = gj < Ncur ? 16 : 0;
            const float* src = Kb + (long long)gj * 2304 + k4;
            cp16(sptr(&Kd[row * FLDK + k4]), src, sz);
            cp16(sptr(&Vd[row * FLDV + k4]), src + 768, sz);
        }
    };

    const int nj = (Ncur + 63) >> 6;
    stageKV(0, 0);
    asm volatile("cp.async.commit_group;");
    asm volatile("cp.async.wait_group 0;");
    __syncthreads();

    uint32_t qf[8][4];
    {
        int row = warp * 16 + r;
        #pragma unroll
        for (int ks = 0; ks < 8; ks++) {
            qf[ks][0] = __float_as_uint(Qs[row       * FLDK + ks * 8 + cq]);
            qf[ks][1] = __float_as_uint(Qs[(row + 8) * FLDK + ks * 8 + cq]);
            qf[ks][2] = __float_as_uint(Qs[row       * FLDK + ks * 8 + cq + 4]);
            qf[ks][3] = __float_as_uint(Qs[(row + 8) * FLDK + ks * 8 + cq + 4]);
        }
    }

    float oacc[8][4];
    #pragma unroll
    for (int i = 0; i < 8; i++)
        #pragma unroll
        for (int q = 0; q < 4; q++) oacc[i][q] = 0.f;
    float mrow[2] = {-1e30f, -1e30f};
    float lrow[2] = {0.f, 0.f};

    for (int j = 0; j < nj; j++) {
        if (j + 1 < nj) {
            stageKV((j + 1) & 1, (j + 1) * 64);
            asm volatile("cp.async.commit_group;");
        }
        const float* Kc = Ks + (j & 1) * 64 * FLDK;
        const float* Vc = Vs + (j & 1) * 64 * FLDV;

        float sacc[8][4];
        #pragma unroll
        for (int i = 0; i < 8; i++)
            #pragma unroll
            for (int q = 0; q < 4; q++) sacc[i][q] = 0.f;
        #pragma unroll
        for (int ks = 0; ks < 8; ks++) {
            #pragma unroll
            for (int nt = 0; nt < 8; nt++) {
                int col = nt * 8 + r;
                uint32_t b0 = __float_as_uint(Kc[col * FLDK + ks * 8 + cq]);
                uint32_t b1 = __float_as_uint(Kc[col * FLDK + ks * 8 + cq + 4]);
                mma_tf32(sacc[nt], qf[ks], b0, b1);
            }
        }

        const int j0 = j * 64;
        float rmax[2] = {-1e30f, -1e30f};
        #pragma unroll
        for (int nt = 0; nt < 8; nt++) {
            #pragma unroll
            for (int q = 0; q < 4; q++) {
                int col = j0 + nt * 8 + cq * 2 + (q & 1);
                float v = (col < Ncur) ? sacc[nt][q] * 0.125f : -1e30f;
                sacc[nt][q] = v;
                rmax[q >> 1] = fmaxf(rmax[q >> 1], v);
            }
        }
        #pragma unroll
        for (int i = 0; i < 2; i++) {
            rmax[i] = fmaxf(rmax[i], __shfl_xor_sync(0xffffffffu, rmax[i], 1));
            rmax[i] = fmaxf(rmax[i], __shfl_xor_sync(0xffffffffu, rmax[i], 2));
        }
        float alpha[2];
        #pragma unroll
        for (int i = 0; i < 2; i++) {
            float mnew = fmaxf(mrow[i], rmax[i]);
            alpha[i] = expf(mrow[i] - mnew);
            mrow[i] = mnew;
        }
        float rsum[2] = {0.f, 0.f};
        #pragma unroll
        for (int nt = 0; nt < 8; nt++)
            #pragma unroll
            for (int q = 0; q < 4; q++) {
                float e = expf(sacc[nt][q] - mrow[q >> 1]);
                sacc[nt][q] = e;
                rsum[q >> 1] += e;
            }
        #pragma unroll
        for (int i = 0; i < 2; i++) {
            rsum[i] += __shfl_xor_sync(0xffffffffu, rsum[i], 1);
            rsum[i] += __shfl_xor_sync(0xffffffffu, rsum[i], 2);
            lrow[i] = lrow[i] * alpha[i] + rsum[i];
        }
        #pragma unroll
        for (int nt = 0; nt < 8; nt++)
            #pragma unroll
            for (int q = 0; q < 4; q++)
                oacc[nt][q] *= alpha[q >> 1];

        #pragma unroll
        for (int nt = 0; nt < 8; nt++) {
            Ps[r       * FLDK + nt * 8 + cq * 2]     = tf32r(sacc[nt][0]);
            Ps[r       * FLDK + nt * 8 + cq * 2 + 1] = tf32r(sacc[nt][1]);
            Ps[(r + 8) * FLDK + nt * 8 + cq * 2]     = tf32r(sacc[nt][2]);
            Ps[(r + 8) * FLDK + nt * 8 + cq * 2 + 1] = tf32r(sacc[nt][3]);
        }
        __syncwarp();
        #pragma unroll
        for (int ks = 0; ks < 8; ks++) {
            uint32_t af[4];
            af[0] = __float_as_uint(Ps[r       * FLDK + ks * 8 + cq]);
            af[1] = __float_as_uint(Ps[(r + 8) * FLDK + ks * 8 + cq]);
            af[2] = __float_as_uint(Ps[r       * FLDK + ks * 8 + cq + 4]);
            af[3] = __float_as_uint(Ps[(r + 8) * FLDK + ks * 8 + cq + 4]);
            #pragma unroll
            for (int nt = 0; nt < 8; nt++) {
                uint32_t b0 = __float_as_uint(Vc[(ks * 8 + cq)     * FLDV + nt * 8 + r]);
                uint32_t b1 = __float_as_uint(Vc[(ks * 8 + cq + 4) * FLDV + nt * 8 + r]);
                mma_tf32(oacc[nt], af, b0, b1);
            }
        }
        __syncwarp();
        if (j + 1 < nj) asm volatile("cp.async.wait_group 0;");
        __syncthreads();
    }

    float inv0 = 1.f / lrow[0], inv1 = 1.f / lrow[1];
    int row0 = q0 + warp * 16 + r;
    #pragma unroll
    for (int nt = 0; nt < 8; nt++) {
        int col = h * 64 + nt * 8 + cq * 2;
        if (row0 < Ncur) {
            float2 o; o.x = tf32r(oacc[nt][0] * inv0); o.y = tf32r(oacc[nt][1] * inv0);
            *reinterpret_cast<float2*>(O + ((long long)b * NTOK + row0) * EMB + col) = o;
        }
        if (row0 + 8 < Ncur) {
            float2 o; o.x = tf32r(oacc[nt][2] * inv1); o.y = tf32r(oacc[nt][3] * inv1);
            *reinterpret_cast<float2*>(O + ((long long)b * NTOK + row0 + 8) * EMB + col) = o;
        }
    }
}

// ---------------------------------------------------------------------------
// LayerNorm over EMB=768 (optionally tf32-round output). Safe for src==dst.
// ---------------------------------------------------------------------------
__global__ void ln_kernel(const float* __restrict__ src, float* __restrict__ dst,
                          const float* __restrict__ g, const float* __restrict__ bb,
                          int roundOut)
{
    long long row = (long long)blockIdx.y * NTOK + blockIdx.x;
    const float* x = src + row * EMB;
    float*       o = dst + row * EMB;
    int t = threadIdx.x;
    __shared__ float sh[8];

    float v0 = x[t], v1 = x[t + 256], v2 = x[t + 512];
    float s = v0 + v1 + v2;
    #pragma unroll
    for (int off = 16; off; off >>= 1) s += __shfl_xor_sync(0xffffffffu, s, off);
    if ((t & 31) == 0) sh[t >> 5] = s;
    __syncthreads();
    float tot = 0.f;
    #pragma unroll
    for (int i = 0; i < 8; i++) tot += sh[i];
    float mu = tot * (1.f / 768.f);

    float d0 = v0 - mu, d1 = v1 - mu, d2 = v2 - mu;
    float q = d0*d0 + d1*d1 + d2*d2;
    #pragma unroll
    for (int off = 16; off; off >>= 1) q += __shfl_xor_sync(0xffffffffu, q, off);
    __syncthreads();
    if ((t & 31) == 0) sh[t >> 5] = q;
    __syncthreads();
    float vt = 0.f;
    #pragma unroll
    for (int i = 0; i < 8; i++) vt += sh[i];
    float inv = rsqrtf(vt * (1.f / 768.f) + 1e-5f);

    float o0 = d0 * inv * g[t]       + bb[t];
    float o1 = d1 * inv * g[t + 256] + bb[t + 256];
    float o2 = d2 * inv * g[t + 512] + bb[t + 512];
    if (roundOut) { o0 = tf32r(o0); o1 = tf32r(o1); o2 = tf32r(o2); }
    o[t] = o0; o[t + 256] = o1; o[t + 512] = o2;
}

// ---------------------------------------------------------------------------
// im2col (tf32-rounded: feeds patch-embed mma A operand)
// ---------------------------------------------------------------------------
__global__ void im2col_kernel(const float* __restrict__ img, float* __restrict__ dst, int imgIdx)
{
    int idx = blockIdx.x * 256 + threadIdx.x;
    if (idx >= BATCH * NPI * EMB) return;
    int k = idx % EMB;
    int p = (idx / EMB) % NPI;
    int b = idx / (EMB * NPI);
    int c  = k / 256;
    int pr = (k / 16) & 15;
    int pc = k & 15;
    int gr = p / 14, gc = p % 14;
    float v = img[(((long long)b * 3 + c) * 224 + gr * 16 + pr) * 224 + gc * 16 + pc];
    dst[((long long)b * NTOK + imgIdx * NPI + p) * EMB + k] = tf32r(v);
}

__global__ void posadd_kernel(float* __restrict__ X, const float* __restrict__ sp,
                              const float* __restrict__ ip)
{
    int idx = blockIdx.x * 256 + threadIdx.x;
    if (idx >= BATCH * NTOK * EMB) return;
    int e = idx % EMB;
    int n = (idx / EMB) % NTOK;
    float add = (e < 384) ? sp[(n % NPI) * 384 + e]
                          : ip[(n / NPI) * 384 + (e - 384)];
    X[idx] += add;
}

__global__ void small_gemm(const float* __restrict__ A, const float* __restrict__ W,
                           const float* __restrict__ bias, float* __restrict__ C,
                           int M, int N, int K, int gelu)
{
    int gt   = blockIdx.x * blockDim.x + threadIdx.x;
    int warp = gt >> 5, lane = gt & 31;
    if (warp >= M * N) return;
    int m = warp / N, n = warp % N;
    float s = 0.f;
    for (int k = lane; k < K; k += 32) s += A[m * K + k] * W[(long long)n * K + k];
    #pragma unroll
    for (int o = 16; o; o >>= 1) s += __shfl_xor_sync(0xffffffffu, s, o);
    if (lane == 0) {
        s += bias[n];
        if (gelu) s = gelu_f(s);
        C[m * N + n] = s;
    }
}

__global__ void mean_kernel(const float* __restrict__ H, float* __restrict__ pool)
{
    int b = blockIdx.x, e = threadIdx.x;
    float s = 0.f;
    for (int n = 0; n < NTOK; n++) s += H[((long long)b * NTOK + n) * EMB + e];
    pool[b * EMB + e] = s * (1.0f / (float)NTOK);
}

__global__ void expand_kernel(const float* __restrict__ pt, float* __restrict__ out)
{
    int idx = blockIdx.x * 256 + threadIdx.x;
    if (idx >= BATCH * 224 * 224) return;
    int c = idx % 224;
    int r = (idx / 224) % 224;
    int b = idx / (224 * 224);
    out[idx] = pt[b * 256 + (r & 15) * 16 + (c & 15)];
}

// ---------------------------------------------------------------------------
// Host orchestration
// ---------------------------------------------------------------------------
extern "C" void kernel_launch(void* const* d_in, const int* in_sizes, int n_in,
                              void* d_out, int out_size)
{
    const float* img[4];
    for (int i = 0; i < 4; i++) img[i] = (const float*)d_in[i];
    const float* pe_w      = (const float*)d_in[4];
    const float* pe_b      = (const float*)d_in[5];
    const float* sp        = (const float*)d_in[6];
    const float* ip        = (const float*)d_in[7];
    const float* ln_attn_g = (const float*)d_in[8];
    const float* ln_attn_b = (const float*)d_in[9];
    const float* qkv_w     = (const float*)d_in[10];
    const float* qkv_b     = (const float*)d_in[11];
    const float* proj_w    = (const float*)d_in[12];
    const float* proj_b    = (const float*)d_in[13];
    const float* ln1_g     = (const float*)d_in[14];
    const float* ln1_b     = (const float*)d_in[15];
    const float* fc1_w     = (const float*)d_in[16];
    const float* fc1_b     = (const float*)d_in[17];
    const float* fc2_w     = (const float*)d_in[18];
    const float* fc2_b     = (const float*)d_in[19];
    const float* ln2_g     = (const float*)d_in[20];
    const float* ln2_b     = (const float*)d_in[21];
    const float* final_g   = (const float*)d_in[22];
    const float* final_b   = (const float*)d_in[23];
    const float* head_w1   = (const float*)d_in[24];
    const float* head_b1   = (const float*)d_in[25];
    const float* head_w2   = (const float*)d_in[26];
    const float* head_b2   = (const float*)d_in[27];
    float* out = (float*)d_out;

    float *X, *H, *FF, *pool, *h1, *pt, *W;
    cudaGetSymbolAddress((void**)&X,    g_X);
    cudaGetSymbolAddress((void**)&H,    g_H);
    cudaGetSymbolAddress((void**)&FF,   g_FF);
    cudaGetSymbolAddress((void**)&pool, g_pool);
    cudaGetSymbolAddress((void**)&h1,   g_h1);
    cudaGetSymbolAddress((void**)&pt,   g_pt);
    cudaGetSymbolAddress((void**)&W,    g_W);

    // 3 stages x (A 128x36 + B 128x36) floats = 110592 B
    const int SMEM_W = 3 * (128*36 + 128*36) * 4;
    cudaFuncSetAttribute(mma_gemm<128,128,2,4,false,false>,
                         cudaFuncAttributeMaxDynamicSharedMemorySize, SMEM_W);
    cudaFuncSetAttribute(mma_gemm<128,128,2,4,false,true>,
                         cudaFuncAttributeMaxDynamicSharedMemorySize, SMEM_W);
    cudaFuncSetAttribute(mma_gemm<128,128,2,4,true,true>,
                         cudaFuncAttributeMaxDynamicSharedMemorySize, SMEM_W);
    cudaFuncSetAttribute(flash_kernel,
                         cudaFuncAttributeMaxDynamicSharedMemorySize, FSM_BYTES);

    const long long SXE = (long long)NTOK * EMB;
    const long long SXQ = (long long)NTOK * 2304;
    const long long SXF = (long long)NTOK * HID;

    // ---- pre-convert all weights to RN tf32 (single launch) ----
    cvt_all_kernel<<<1024, 256>>>((const float4*)pe_w, (const float4*)qkv_w,
                                  (const float4*)proj_w, (const float4*)fc1_w,
                                  (const float4*)fc2_w, (float4*)W);

    // ---- patch embed + positional encode ----
    {
        int total = BATCH * NPI * EMB;
        for (int i = 0; i < 4; i++)
            im2col_kernel<<<(total + 255) / 256, 256>>>(img[i], FF, i);
        for (int i = 0; i < 4; i++) {
            mma_gemm<128,128,2,4,false,false><<<dim3(2, 6, BATCH), 256, SMEM_W>>>(
                FF + (long long)i * NPI * EMB, EMB, SXE,
                W + OFF_PE + (long long)i * EMB * EMB, EMB, 0,
                X + (long long)i * NPI * EMB, EMB, SXE,
                pe_b + i * EMB, nullptr, 0,
                NPI, EMB, EMB, 1.f);
        }
        int tot2 = BATCH * NTOK * EMB;
        posadd_kernel<<<(tot2 + 255) / 256, 256>>>(X, sp, ip);
    }

    // ---- transformer blocks ----
    for (int blk = 0; blk < 3; blk++) {
        int Ncur = 392 + 196 * blk;
        int mt128 = (Ncur + 127) / 128;
        int nqt   = (Ncur + 63) / 64;

        ln_kernel<<<dim3(Ncur, BATCH), 256>>>(X, H, ln_attn_g + blk*EMB, ln_attn_b + blk*EMB, 1);

        // QKV (rounded out: feeds flash)
        mma_gemm<128,128,2,4,false,true><<<dim3(mt128, 18, BATCH), 256, SMEM_W>>>(
            H, EMB, SXE,
            W + OFF_QKV + (long long)blk * 2304 * EMB, EMB, 0,
            FF, 2304, SXQ,
            qkv_b + blk * 2304, nullptr, 0,
            Ncur, 2304, EMB, 1.f);

        // fused attention -> H
        flash_kernel<<<dim3(nqt, BATCH * NHEAD), 128, FSM_BYTES>>>(FF, H, Ncur);

        // X = X + O @ proj_w^T + proj_b
        mma_gemm<128,128,2,4,false,false><<<dim3(mt128, 6, BATCH), 256, SMEM_W>>>(
            H, EMB, SXE,
            W + OFF_PROJ + (long long)blk * EMB * EMB, EMB, 0,
            X, EMB, SXE,
            proj_b + blk * EMB, X, SXE,
            Ncur, EMB, EMB, 1.f);

        ln_kernel<<<dim3(Ncur, BATCH), 256>>>(X, H, ln1_g + blk*EMB, ln1_b + blk*EMB, 1);

        // FF = gelu(H @ fc1_w^T + fc1_b) (rounded out)
        mma_gemm<128,128,2,4,true,true><<<dim3(mt128, 24, BATCH), 256, SMEM_W>>>(
            H, EMB, SXE,
            W + OFF_FC1 + (long long)blk * HID * EMB, EMB, 0,
            FF, HID, SXF,
            fc1_b + blk * HID, nullptr, 0,
            Ncur, HID, EMB, 1.f);

        // X = X + FF @ fc2_w^T + fc2_b
        mma_gemm<128,128,2,4,false,false><<<dim3(mt128, 6, BATCH), 256, SMEM_W>>>(
            FF, HID, SXF,
            W + OFF_FC2 + (long long)blk * EMB * HID, HID, 0,
            X, EMB, SXE,
            fc2_b + blk * EMB, X, SXE,
            Ncur, EMB, HID, 1.f);

        // LN2 in place (full fp32 state, no rounding)
        ln_kernel<<<dim3(Ncur, BATCH), 256>>>(X, X, ln2_g + blk*EMB, ln2_b + blk*EMB, 0);
    }

    // ---- final LN, mean-pool, head, expand ----
    ln_kernel<<<dim3(NTOK, BATCH), 256>>>(X, H, final_g, final_b, 0);
    mean_kernel<<<BATCH, EMB>>>(H, pool);
    small_gemm<<<(BATCH * EMB * 32 + 255) / 256, 256>>>(pool, head_w1, head_b1, h1,
                                                        BATCH, EMB, EMB, 1);
    small_gemm<<<(BATCH * 256 * 32 + 255) / 256, 256>>>(h1, head_w2, head_b2, pt,
                                                        BATCH, 256, EMB, 0);
    expand_kernel<<<(BATCH * 224 * 224 + 255) / 256, 256>>>(pt, out);
}

// round 14
// speedup vs baseline: 1.1899x; 1.0784x over previous
#include <cuda_runtime.h>
#include <math.h>
#include <stdint.h>

// ---------------------------------------------------------------------------
// Shapes
// ---------------------------------------------------------------------------
#define BATCH 8
#define EMB   768
#define NTOK  784
#define NPI   196
#define NHEAD 12
#define HD    64
#define HID   3072

// ---------------------------------------------------------------------------
// Scratch (device globals — no allocation allowed)
// ---------------------------------------------------------------------------
__device__ float g_X [BATCH * NTOK * EMB];
__device__ float g_H [BATCH * NTOK * EMB];
__device__ float g_FF[BATCH * NTOK * HID];
__device__ float g_pool[BATCH * EMB];
__device__ float g_h1 [BATCH * EMB];
__device__ float g_pt [BATCH * 256];
// tf32-rounded weights (pe_w | qkv_w | proj_w | fc1_w | fc2_w)
#define OFF_PE   0
#define OFF_QKV  2359296
#define OFF_PROJ 7667712
#define OFF_FC1  9437184
#define OFF_FC2  16515072
#define W_TOTAL  23592960
__device__ float g_W[W_TOTAL];

__device__ __forceinline__ float gelu_f(float x) {
    return 0.5f * x * (1.0f + erff(x * 0.7071067811865475f));
}
__device__ __forceinline__ float tf32r(float f) {
    uint32_t u;
    asm("cvt.rna.tf32.f32 %0, %1;" : "=r"(u) : "f"(f));
    return __uint_as_float(u);
}
__device__ __forceinline__ uint32_t sptr(const void* p) {
    return (uint32_t)__cvta_generic_to_shared(p);
}
__device__ __forceinline__ void cp16(uint32_t dst, const void* src, int sz) {
    asm volatile("cp.async.cg.shared.global [%0], [%1], 16, %2;"
                 :: "r"(dst), "l"(src), "r"(sz));
}
__device__ __forceinline__ void mma_tf32(float* d, const uint32_t* a,
                                         uint32_t b0, uint32_t b1) {
    asm volatile(
        "mma.sync.aligned.m16n8k8.row.col.f32.tf32.tf32.f32 "
        "{%0,%1,%2,%3}, {%4,%5,%6,%7}, {%8,%9}, {%0,%1,%2,%3};"
        : "+f"(d[0]), "+f"(d[1]), "+f"(d[2]), "+f"(d[3])
        : "r"(a[0]), "r"(a[1]), "r"(a[2]), "r"(a[3]), "r"(b0), "r"(b1));
}
__device__ __forceinline__ void ldsm4(uint32_t* r, uint32_t addr) {
    asm volatile("ldmatrix.sync.aligned.m8n8.x4.shared.b16 {%0,%1,%2,%3}, [%4];"
                 : "=r"(r[0]), "=r"(r[1]), "=r"(r[2]), "=r"(r[3]) : "r"(addr));
}

// ---------------------------------------------------------------------------
// Weight pre-convert (fp32 -> RN tf32), one launch, segmented.
// ---------------------------------------------------------------------------
__global__ void cvt_all_kernel(const float4* __restrict__ s0, const float4* __restrict__ s1,
                               const float4* __restrict__ s2, const float4* __restrict__ s3,
                               const float4* __restrict__ s4, float4* __restrict__ dst)
{
    const int b0 = OFF_QKV / 4, b1 = OFF_PROJ / 4, b2 = OFF_FC1 / 4,
              b3 = OFF_FC2 / 4, b4 = W_TOTAL / 4;
    int i = blockIdx.x * blockDim.x + threadIdx.x;
    int stride = gridDim.x * blockDim.x;
    for (; i < b4; i += stride) {
        const float4* src;
        int off;
        if      (i < b0) { src = s0; off = i; }
        else if (i < b1) { src = s1; off = i - b0; }
        else if (i < b2) { src = s2; off = i - b1; }
        else if (i < b3) { src = s3; off = i - b2; }
        else             { src = s4; off = i - b3; }
        float4 v = src[off];
        v.x = tf32r(v.x); v.y = tf32r(v.y); v.z = tf32r(v.z); v.w = tf32r(v.w);
        dst[i] = v;
    }
}

// ---------------------------------------------------------------------------
// TF32 tensor-core GEMM: 3-stage cp.async pipeline + ldmatrix frag loads.
// B row-major-K, tiles [n][LK]. Batch z decomposed z1=z/nb2, z2=z%nb2:
//   A + z1*sA1 + z2*sA2, B + z1*sB1, C + z1*sC1 + z2*sC2, bias + z1*sBias.
// POSENC: epilogue adds concat(spatial_pos[token], image_pos[z1]) (patch embed).
// ---------------------------------------------------------------------------
template<int BM, int BN, int WR, int WC, bool GELU, bool ROUND, bool POSENC>
__global__ __launch_bounds__(WR*WC*32)
void mma_gemm(const float* __restrict__ A, int lda, long long sA1, long long sA2,
              const float* __restrict__ Bm, int ldb, long long sB1,
              float* __restrict__ C, int ldc, long long sC1, long long sC2,
              const float* __restrict__ bias, long long sBias,
              const float* __restrict__ res, long long sRes,
              const float* __restrict__ sp, const float* __restrict__ ip,
              int M, int N, int K, int nb2, float scale)
{
    constexpr int BK      = 32;
    constexpr int THREADS = WR * WC * 32;
    constexpr int WTM     = BM / WR;
    constexpr int WTN     = BN / WC;
    constexpr int MT      = WTM / 16;
    constexpr int NT      = WTN / 8;
    constexpr int LK      = BK + 4;       // 36 floats: LDSM phases conflict-free
    constexpr int ASZ     = BM * LK;
    constexpr int BSZ     = BN * LK;
    constexpr int STAGES  = 3;

    extern __shared__ float smem[];
    float* As = smem;
    float* Bs = smem + STAGES * ASZ;

    const int z  = blockIdx.z;
    const int z1 = z / nb2;
    const int z2 = z - z1 * nb2;
    const float* Ab = A  + (long long)z1 * sA1 + (long long)z2 * sA2;
    const float* Bb = Bm + (long long)z1 * sB1;
    float*       Cb = C  + (long long)z1 * sC1 + (long long)z2 * sC2;
    const float* biasz = bias ? bias + (long long)z1 * sBias : nullptr;

    const int tid  = threadIdx.x;
    const int lane = tid & 31;
    const int warp = tid >> 5;
    const int wm   = warp / WC;
    const int wn   = warp % WC;
    const int m0   = blockIdx.x * BM;
    const int n0   = blockIdx.y * BN;
    const int r    = lane >> 2;
    const int cq   = lane & 3;

    float acc[MT][NT][4];
    #pragma unroll
    for (int i = 0; i < MT; i++)
        #pragma unroll
        for (int j = 0; j < NT; j++)
            #pragma unroll
            for (int q = 0; q < 4; q++) acc[i][j][q] = 0.f;

    auto stage = [&](int buf, int k0) {
        float* Ad = As + buf * ASZ;
        #pragma unroll
        for (int i = 0; i < (BM*(BK/4))/THREADS; i++) {
            int cid = tid + i * THREADS;
            int m   = cid >> 3;
            int k4  = (cid & 7) << 2;
            int gm  = m0 + m, gk = k0 + k4;
            int sz  = (gm < M && gk < K) ? 16 : 0;
            cp16(sptr(&Ad[m * LK + k4]), Ab + (long long)gm * lda + gk, sz);
        }
        float* Bd = Bs + buf * BSZ;
        #pragma unroll
        for (int i = 0; i < (BN*(BK/4))/THREADS; i++) {
            int cid = tid + i * THREADS;
            int n   = cid >> 3;
            int k4  = (cid & 7) << 2;
            int gn  = n0 + n, gk = k0 + k4;
            int sz  = (gn < N && gk < K) ? 16 : 0;
            cp16(sptr(&Bd[n * LK + k4]), Bb + (long long)gn * ldb + gk, sz);
        }
    };

    const int nk = (K + BK - 1) / BK;
    stage(0, 0);
    asm volatile("cp.async.commit_group;");
    if (nk > 1) stage(1, BK);
    asm volatile("cp.async.commit_group;");

    const int a_row = (lane & 15);
    const int a_kc  = (lane >> 4) << 2;
    const int b_col = ((lane >> 4) << 3) + (lane & 7);
    const int b_kc  = ((lane >> 3) & 1) << 2;

    for (int t = 0; t < nk; t++) {
        asm volatile("cp.async.wait_group 1;");
        __syncthreads();
        if (t + 2 < nk) stage((t + 2) % STAGES, (t + 2) * BK);
        asm volatile("cp.async.commit_group;");

        const float* Ac = As + (t % STAGES) * ASZ;
        const float* Bc = Bs + (t % STAGES) * BSZ;

        #pragma unroll
        for (int kk = 0; kk < BK; kk += 8) {
            uint32_t af[MT][4];
            uint32_t bf[NT][2];
            #pragma unroll
            for (int mt = 0; mt < MT; mt++) {
                int row = wm * WTM + mt * 16 + a_row;
                ldsm4(af[mt], sptr(&Ac[row * LK + kk + a_kc]));
            }
            #pragma unroll
            for (int np = 0; np < NT; np += 2) {
                int col = wn * WTN + np * 8 + b_col;
                uint32_t tmp[4];
                ldsm4(tmp, sptr(&Bc[col * LK + kk + b_kc]));
                bf[np][0]     = tmp[0]; bf[np][1]     = tmp[1];
                bf[np + 1][0] = tmp[2]; bf[np + 1][1] = tmp[3];
            }
            #pragma unroll
            for (int mt = 0; mt < MT; mt++)
                #pragma unroll
                for (int nt = 0; nt < NT; nt++)
                    mma_tf32(acc[mt][nt], af[mt], bf[nt][0], bf[nt][1]);
        }
    }
    __syncthreads();

    // epilogue: float2-vectorized (N % BN == 0 for all uses)
    #pragma unroll
    for (int mt = 0; mt < MT; mt++) {
        #pragma unroll
        for (int i = 0; i < 2; i++) {
            int gm = m0 + wm * WTM + mt * 16 + r + i * 8;
            if (gm >= M) continue;
            #pragma unroll
            for (int nt = 0; nt < NT; nt++) {
                int gn = n0 + wn * WTN + nt * 8 + cq * 2;
                if (gn + 1 >= N) continue;
                float v0 = acc[mt][nt][i * 2 + 0] * scale;
                float v1 = acc[mt][nt][i * 2 + 1] * scale;
                if (biasz) {
                    float2 bb = *reinterpret_cast<const float2*>(&biasz[gn]);
                    v0 += bb.x; v1 += bb.y;
                }
                if (GELU) { v0 = gelu_f(v0); v1 = gelu_f(v1); }
                if (POSENC) {
                    float2 ad = (gn < 384)
                        ? *reinterpret_cast<const float2*>(&sp[gm * 384 + gn])
                        : *reinterpret_cast<const float2*>(&ip[z1 * 384 + gn - 384]);
                    v0 += ad.x; v1 += ad.y;
                }
                if (res) {
                    float2 rr = *reinterpret_cast<const float2*>(
                        &res[(long long)z * sRes + (long long)gm * ldc + gn]);
                    v0 += rr.x; v1 += rr.y;
                }
                if (ROUND) { v0 = tf32r(v0); v1 = tf32r(v1); }
                float2 o; o.x = v0; o.y = v1;
                *reinterpret_cast<float2*>(&Cb[(long long)gm * ldc + gn]) = o;
            }
        }
    }
}

// ---------------------------------------------------------------------------
// Flash attention: per (b,h,q-tile 64). 4 warps x 16 q-rows. HD=64.
// ldmatrix for K B-frags and P A-frags; V stays scalar ([k][n] layout).
// ---------------------------------------------------------------------------
#define FLDK 68
#define FLDV 72
#define FQS  0
#define FKS  (64*FLDK)
#define FVS  (FKS + 2*64*FLDK)
#define FPS  (FVS + 2*64*FLDV)
#define FSM_FLOATS (FPS + 4*16*FLDK)
#define FSM_BYTES  (FSM_FLOATS*4)

__global__ __launch_bounds__(128)
void flash_kernel(const float* __restrict__ QKV, float* __restrict__ O, int Ncur)
{
    const int qt  = blockIdx.x;
    const int bh  = blockIdx.y;
    const int b   = bh / NHEAD;
    const int h   = bh % NHEAD;
    const int tid = threadIdx.x;
    const int warp = tid >> 5, lane = tid & 31;
    const int r = lane >> 2, cq = lane & 3;

    extern __shared__ float sm[];
    float* Qs = sm + FQS;
    float* Ks = sm + FKS;
    float* Vs = sm + FVS;
    float* Ps = sm + FPS + warp * 16 * FLDK;

    const float* Qb = QKV + (long long)b * NTOK * 2304 + h * 64;
    const float* Kb = Qb + 768;
    const int q0 = qt * 64;

    for (int i = tid; i < 64 * 16; i += 128) {
        int row = i >> 4, k4 = (i & 15) << 2;
        int gq = q0 + row;
        cp16(sptr(&Qs[row * FLDK + k4]), Qb + (long long)gq * 2304 + k4,
             gq < Ncur ? 16 : 0);
    }
    auto stageKV = [&](int buf, int j0) {
        float* Kd = Ks + buf * 64 * FLDK;
        float* Vd = Vs + buf * 64 * FLDV;
        for (int i = tid; i < 64 * 16; i += 128) {
            int row = i >> 4, k4 = (i & 15) << 2;
            int gj = j0 + row;
            int sz = gj < Ncur ? 16 : 0;
            const float* src = Kb + (long long)gj * 2304 + k4;
            cp16(sptr(&Kd[row * FLDK + k4]), src, sz);
            cp16(sptr(&Vd[row * FLDV + k4]), src + 768, sz);
        }
    };

    const int nj = (Ncur + 63) >> 6;
    stageKV(0, 0);
    asm volatile("cp.async.commit_group;");
    asm volatile("cp.async.wait_group 0;");
    __syncthreads();

    uint32_t qf[8][4];
    {
        int row = warp * 16 + r;
        #pragma unroll
        for (int ks = 0; ks < 8; ks++) {
            qf[ks][0] = __float_as_uint(Qs[row       * FLDK + ks * 8 + cq]);
            qf[ks][1] = __float_as_uint(Qs[(row + 8) * FLDK + ks * 8 + cq]);
            qf[ks][2] = __float_as_uint(Qs[row       * FLDK + ks * 8 + cq + 4]);
            qf[ks][3] = __float_as_uint(Qs[(row + 8) * FLDK + ks * 8 + cq + 4]);
        }
    }

    // ldmatrix lane addressing
    const int a_row = (lane & 15);
    const int a_kc  = (lane >> 4) << 2;
    const int b_col = ((lane >> 4) << 3) + (lane & 7);
    const int b_kc  = ((lane >> 3) & 1) << 2;

    float oacc[8][4];
    #pragma unroll
    for (int i = 0; i < 8; i++)
        #pragma unroll
        for (int q = 0; q < 4; q++) oacc[i][q] = 0.f;
    float mrow[2] = {-1e30f, -1e30f};
    float lrow[2] = {0.f, 0.f};

    for (int j = 0; j < nj; j++) {
        if (j + 1 < nj) {
            stageKV((j + 1) & 1, (j + 1) * 64);
            asm volatile("cp.async.commit_group;");
        }
        const float* Kc = Ks + (j & 1) * 64 * FLDK;
        const float* Vc = Vs + (j & 1) * 64 * FLDV;

        float sacc[8][4];
        #pragma unroll
        for (int i = 0; i < 8; i++)
            #pragma unroll
            for (int q = 0; q < 4; q++) sacc[i][q] = 0.f;
        #pragma unroll
        for (int ks = 0; ks < 8; ks++) {
            uint32_t bf[8][2];
            #pragma unroll
            for (int np = 0; np < 8; np += 2) {
                int col = np * 8 + b_col;
                uint32_t tmp[4];
                ldsm4(tmp, sptr(&Kc[col * FLDK + ks * 8 + b_kc]));
                bf[np][0]     = tmp[0]; bf[np][1]     = tmp[1];
                bf[np + 1][0] = tmp[2]; bf[np + 1][1] = tmp[3];
            }
            #pragma unroll
            for (int nt = 0; nt < 8; nt++)
                mma_tf32(sacc[nt], qf[ks], bf[nt][0], bf[nt][1]);
        }

        const int j0 = j * 64;
        float rmax[2] = {-1e30f, -1e30f};
        #pragma unroll
        for (int nt = 0; nt < 8; nt++) {
            #pragma unroll
            for (int q = 0; q < 4; q++) {
                int col = j0 + nt * 8 + cq * 2 + (q & 1);
                float v = (col < Ncur) ? sacc[nt][q] * 0.125f : -1e30f;
                sacc[nt][q] = v;
                rmax[q >> 1] = fmaxf(rmax[q >> 1], v);
            }
        }
        #pragma unroll
        for (int i = 0; i < 2; i++) {
            rmax[i] = fmaxf(rmax[i], __shfl_xor_sync(0xffffffffu, rmax[i], 1));
            rmax[i] = fmaxf(rmax[i], __shfl_xor_sync(0xffffffffu, rmax[i], 2));
        }
        float alpha[2];
        #pragma unroll
        for (int i = 0; i < 2; i++) {
            float mnew = fmaxf(mrow[i], rmax[i]);
            alpha[i] = expf(mrow[i] - mnew);
            mrow[i] = mnew;
        }
        float rsum[2] = {0.f, 0.f};
        #pragma unroll
        for (int nt = 0; nt < 8; nt++)
            #pragma unroll
            for (int q = 0; q < 4; q++) {
                float e = expf(sacc[nt][q] - mrow[q >> 1]);
                sacc[nt][q] = e;
                rsum[q >> 1] += e;
            }
        #pragma unroll
        for (int i = 0; i < 2; i++) {
            rsum[i] += __shfl_xor_sync(0xffffffffu, rsum[i], 1);
            rsum[i] += __shfl_xor_sync(0xffffffffu, rsum[i], 2);
            lrow[i] = lrow[i] * alpha[i] + rsum[i];
        }
        #pragma unroll
        for (int nt = 0; nt < 8; nt++)
            #pragma unroll
            for (int q = 0; q < 4; q++)
                oacc[nt][q] *= alpha[q >> 1];

        #pragma unroll
        for (int nt = 0; nt < 8; nt++) {
            Ps[r       * FLDK + nt * 8 + cq * 2]     = tf32r(sacc[nt][0]);
            Ps[r       * FLDK + nt * 8 + cq * 2 + 1] = tf32r(sacc[nt][1]);
            Ps[(r + 8) * FLDK + nt * 8 + cq * 2]     = tf32r(sacc[nt][2]);
            Ps[(r + 8) * FLDK + nt * 8 + cq * 2 + 1] = tf32r(sacc[nt][3]);
        }
        __syncwarp();
        #pragma unroll
        for (int ks = 0; ks < 8; ks++) {
            uint32_t af[4];
            ldsm4(af, sptr(&Ps[a_row * FLDK + ks * 8 + a_kc]));
            #pragma unroll
            for (int nt = 0; nt < 8; nt++) {
                uint32_t b0 = __float_as_uint(Vc[(ks * 8 + cq)     * FLDV + nt * 8 + r]);
                uint32_t b1 = __float_as_uint(Vc[(ks * 8 + cq + 4) * FLDV + nt * 8 + r]);
                mma_tf32(oacc[nt], af, b0, b1);
            }
        }
        __syncwarp();
        if (j + 1 < nj) asm volatile("cp.async.wait_group 0;");
        __syncthreads();
    }

    float inv0 = 1.f / lrow[0], inv1 = 1.f / lrow[1];
    int row0 = q0 + warp * 16 + r;
    #pragma unroll
    for (int nt = 0; nt < 8; nt++) {
        int col = h * 64 + nt * 8 + cq * 2;
        if (row0 < Ncur) {
            float2 o; o.x = tf32r(oacc[nt][0] * inv0); o.y = tf32r(oacc[nt][1] * inv0);
            *reinterpret_cast<float2*>(O + ((long long)b * NTOK + row0) * EMB + col) = o;
        }
        if (row0 + 8 < Ncur) {
            float2 o; o.x = tf32r(oacc[nt][2] * inv1); o.y = tf32r(oacc[nt][3] * inv1);
            *reinterpret_cast<float2*>(O + ((long long)b * NTOK + row0 + 8) * EMB + col) = o;
        }
    }
}

// ---------------------------------------------------------------------------
// LayerNorm over EMB=768 (optionally tf32-round output). Safe for src==dst.
// ---------------------------------------------------------------------------
__global__ void ln_kernel(const float* __restrict__ src, float* __restrict__ dst,
                          const float* __restrict__ g, const float* __restrict__ bb,
                          int roundOut)
{
    long long row = (long long)blockIdx.y * NTOK + blockIdx.x;
    const float* x = src + row * EMB;
    float*       o = dst + row * EMB;
    int t = threadIdx.x;
    __shared__ float sh[8];

    float v0 = x[t], v1 = x[t + 256], v2 = x[t + 512];
    float s = v0 + v1 + v2;
    #pragma unroll
    for (int off = 16; off; off >>= 1) s += __shfl_xor_sync(0xffffffffu, s, off);
    if ((t & 31) == 0) sh[t >> 5] = s;
    __syncthreads();
    float tot = 0.f;
    #pragma unroll
    for (int i = 0; i < 8; i++) tot += sh[i];
    float mu = tot * (1.f / 768.f);

    float d0 = v0 - mu, d1 = v1 - mu, d2 = v2 - mu;
    float q = d0*d0 + d1*d1 + d2*d2;
    #pragma unroll
    for (int off = 16; off; off >>= 1) q += __shfl_xor_sync(0xffffffffu, q, off);
    __syncthreads();
    if ((t & 31) == 0) sh[t >> 5] = q;
    __syncthreads();
    float vt = 0.f;
    #pragma unroll
    for (int i = 0; i < 8; i++) vt += sh[i];
    float inv = rsqrtf(vt * (1.f / 768.f) + 1e-5f);

    float o0 = d0 * inv * g[t]       + bb[t];
    float o1 = d1 * inv * g[t + 256] + bb[t + 256];
    float o2 = d2 * inv * g[t + 512] + bb[t + 512];
    if (roundOut) { o0 = tf32r(o0); o1 = tf32r(o1); o2 = tf32r(o2); }
    o[t] = o0; o[t + 256] = o1; o[t + 512] = o2;
}

// ---------------------------------------------------------------------------
// im2col, all 4 images in one launch (blockIdx.y = image).
// ---------------------------------------------------------------------------
__global__ void im2col_all_kernel(const float* __restrict__ i0, const float* __restrict__ i1,
                                  const float* __restrict__ i2, const float* __restrict__ i3,
                                  float* __restrict__ dst)
{
    int idx = blockIdx.x * 256 + threadIdx.x;
    if (idx >= BATCH * NPI * EMB) return;
    int imgIdx = blockIdx.y;
    const float* img = (imgIdx == 0) ? i0 : (imgIdx == 1) ? i1 : (imgIdx == 2) ? i2 : i3;
    int k = idx % EMB;
    int p = (idx / EMB) % NPI;
    int b = idx / (EMB * NPI);
    int c  = k / 256;
    int pr = (k / 16) & 15;
    int pc = k & 15;
    int gr = p / 14, gc = p % 14;
    float v = img[(((long long)b * 3 + c) * 224 + gr * 16 + pr) * 224 + gc * 16 + pc];
    dst[((long long)b * NTOK + imgIdx * NPI + p) * EMB + k] = tf32r(v);
}

__global__ void small_gemm(const float* __restrict__ A, const float* __restrict__ W,
                           const float* __restrict__ bias, float* __restrict__ C,
                           int M, int N, int K, int gelu)
{
    int gt   = blockIdx.x * blockDim.x + threadIdx.x;
    int warp = gt >> 5, lane = gt & 31;
    if (warp >= M * N) return;
    int m = warp / N, n = warp % N;
    float s = 0.f;
    for (int k = lane; k < K; k += 32) s += A[m * K + k] * W[(long long)n * K + k];
    #pragma unroll
    for (int o = 16; o; o >>= 1) s += __shfl_xor_sync(0xffffffffu, s, o);
    if (lane == 0) {
        s += bias[n];
        if (gelu) s = gelu_f(s);
        C[m * N + n] = s;
    }
}

__global__ void mean_kernel(const float* __restrict__ H, float* __restrict__ pool)
{
    int b = blockIdx.x, e = threadIdx.x;
    float s = 0.f;
    for (int n = 0; n < NTOK; n++) s += H[((long long)b * NTOK + n) * EMB + e];
    pool[b * EMB + e] = s * (1.0f / (float)NTOK);
}

__global__ void expand_kernel(const float* __restrict__ pt, float* __restrict__ out)
{
    int idx = blockIdx.x * 256 + threadIdx.x;
    if (idx >= BATCH * 224 * 224) return;
    int c = idx % 224;
    int r = (idx / 224) % 224;
    int b = idx / (224 * 224);
    out[idx] = pt[b * 256 + (r & 15) * 16 + (c & 15)];
}

// ---------------------------------------------------------------------------
// Host orchestration
// ---------------------------------------------------------------------------
extern "C" void kernel_launch(void* const* d_in, const int* in_sizes, int n_in,
                              void* d_out, int out_size)
{
    const float* img[4];
    for (int i = 0; i < 4; i++) img[i] = (const float*)d_in[i];
    const float* pe_w      = (const float*)d_in[4];
    const float* pe_b      = (const float*)d_in[5];
    const float* sp        = (const float*)d_in[6];
    const float* ip        = (const float*)d_in[7];
    const float* ln_attn_g = (const float*)d_in[8];
    const float* ln_attn_b = (const float*)d_in[9];
    const float* qkv_w     = (const float*)d_in[10];
    const float* qkv_b     = (const float*)d_in[11];
    const float* proj_w    = (const float*)d_in[12];
    const float* proj_b    = (const float*)d_in[13];
    const float* ln1_g     = (const float*)d_in[14];
    const float* ln1_b     = (const float*)d_in[15];
    const float* fc1_w     = (const float*)d_in[16];
    const float* fc1_b     = (const float*)d_in[17];
    const float* fc2_w     = (const float*)d_in[18];
    const float* fc2_b     = (const float*)d_in[19];
    const float* ln2_g     = (const float*)d_in[20];
    const float* ln2_b     = (const float*)d_in[21];
    const float* final_g   = (const float*)d_in[22];
    const float* final_b   = (const float*)d_in[23];
    const float* head_w1   = (const float*)d_in[24];
    const float* head_b1   = (const float*)d_in[25];
    const float* head_w2   = (const float*)d_in[26];
    const float* head_b2   = (const float*)d_in[27];
    float* out = (float*)d_out;

    float *X, *H, *FF, *pool, *h1, *pt, *W;
    cudaGetSymbolAddress((void**)&X,    g_X);
    cudaGetSymbolAddress((void**)&H,    g_H);
    cudaGetSymbolAddress((void**)&FF,   g_FF);
    cudaGetSymbolAddress((void**)&pool, g_pool);
    cudaGetSymbolAddress((void**)&h1,   g_h1);
    cudaGetSymbolAddress((void**)&pt,   g_pt);
    cudaGetSymbolAddress((void**)&W,    g_W);

    // 3 stages x (A 128x36 + B 128x36) floats = 110592 B
    const int SMEM_W = 3 * (128*36 + 128*36) * 4;
    cudaFuncSetAttribute(mma_gemm<128,128,2,4,false,false,false>,
                         cudaFuncAttributeMaxDynamicSharedMemorySize, SMEM_W);
    cudaFuncSetAttribute(mma_gemm<128,128,2,4,false,true,false>,
                         cudaFuncAttributeMaxDynamicSharedMemorySize, SMEM_W);
    cudaFuncSetAttribute(mma_gemm<128,128,2,4,true,true,false>,
                         cudaFuncAttributeMaxDynamicSharedMemorySize, SMEM_W);
    cudaFuncSetAttribute(mma_gemm<128,128,2,4,false,false,true>,
                         cudaFuncAttributeMaxDynamicSharedMemorySize, SMEM_W);
    cudaFuncSetAttribute(flash_kernel,
                         cudaFuncAttributeMaxDynamicSharedMemorySize, FSM_BYTES);

    const long long SXE = (long long)NTOK * EMB;
    const long long SXQ = (long long)NTOK * 2304;
    const long long SXF = (long long)NTOK * HID;

    // ---- pre-convert all weights to RN tf32 (single launch) ----
    cvt_all_kernel<<<1024, 256>>>((const float4*)pe_w, (const float4*)qkv_w,
                                  (const float4*)proj_w, (const float4*)fc1_w,
                                  (const float4*)fc2_w, (float4*)W);

    // ---- patch embed (one im2col + one batched GEMM, pos-enc fused) ----
    {
        int total = BATCH * NPI * EMB;
        im2col_all_kernel<<<dim3((total + 255) / 256, 4), 256>>>(
            img[0], img[1], img[2], img[3], FF);
        // z = imgIdx*BATCH + b
        mma_gemm<128,128,2,4,false,false,true><<<dim3(2, 6, 4 * BATCH), 256, SMEM_W>>>(
            FF, EMB, (long long)NPI * EMB, SXE,
            W + OFF_PE, EMB, (long long)EMB * EMB,
            X, EMB, (long long)NPI * EMB, SXE,
            pe_b, EMB, nullptr, 0,
            sp, ip,
            NPI, EMB, EMB, BATCH, 1.f);
    }

    // ---- transformer blocks ----
    for (int blk = 0; blk < 3; blk++) {
        int Ncur = 392 + 196 * blk;
        int mt128 = (Ncur + 127) / 128;
        int nqt   = (Ncur + 63) / 64;

        ln_kernel<<<dim3(Ncur, BATCH), 256>>>(X, H, ln_attn_g + blk*EMB, ln_attn_b + blk*EMB, 1);

        // QKV (rounded out: feeds flash)
        mma_gemm<128,128,2,4,false,true,false><<<dim3(mt128, 18, BATCH), 256, SMEM_W>>>(
            H, EMB, SXE, 0,
            W + OFF_QKV + (long long)blk * 2304 * EMB, EMB, 0,
            FF, 2304, SXQ, 0,
            qkv_b + blk * 2304, 0, nullptr, 0,
            nullptr, nullptr,
            Ncur, 2304, EMB, 1, 1.f);

        // fused attention -> H
        flash_kernel<<<dim3(nqt, BATCH * NHEAD), 128, FSM_BYTES>>>(FF, H, Ncur);

        // X = X + O @ proj_w^T + proj_b
        mma_gemm<128,128,2,4,false,false,false><<<dim3(mt128, 6, BATCH), 256, SMEM_W>>>(
            H, EMB, SXE, 0,
            W + OFF_PROJ + (long long)blk * EMB * EMB, EMB, 0,
            X, EMB, SXE, 0,
            proj_b + blk * EMB, 0, X, SXE,
            nullptr, nullptr,
            Ncur, EMB, EMB, 1, 1.f);

        ln_kernel<<<dim3(Ncur, BATCH), 256>>>(X, H, ln1_g + blk*EMB, ln1_b + blk*EMB, 1);

        // FF = gelu(H @ fc1_w^T + fc1_b) (rounded out)
        mma_gemm<128,128,2,4,true,true,false><<<dim3(mt128, 24, BATCH), 256, SMEM_W>>>(
            H, EMB, SXE, 0,
            W + OFF_FC1 + (long long)blk * HID * EMB, EMB, 0,
            FF, HID, SXF, 0,
            fc1_b + blk * HID, 0, nullptr, 0,
            nullptr, nullptr,
            Ncur, HID, EMB, 1, 1.f);

        // X = X + FF @ fc2_w^T + fc2_b
        mma_gemm<128,128,2,4,false,false,false><<<dim3(mt128, 6, BATCH), 256, SMEM_W>>>(
            FF, HID, SXF, 0,
            W + OFF_FC2 + (long long)blk * EMB * HID, HID, 0,
            X, EMB, SXE, 0,
            fc2_b + blk * EMB, 0, X, SXE,
            nullptr, nullptr,
            Ncur, EMB, HID, 1, 1.f);

        // LN2 in place (full fp32 state, no rounding)
        ln_kernel<<<dim3(Ncur, BATCH), 256>>>(X, X, ln2_g + blk*EMB, ln2_b + blk*EMB, 0);
    }

    // ---- final LN, mean-pool, head, expand ----
    ln_kernel<<<dim3(NTOK, BATCH), 256>>>(X, H, final_g, final_b, 0);
    mean_kernel<<<BATCH, EMB>>>(H, pool);
    small_gemm<<<(BATCH * EMB * 32 + 255) / 256, 256>>>(pool, head_w1, head_b1, h1,
                                                        BATCH, EMB, EMB, 1);
    small_gemm<<<(BATCH * 256 * 32 + 255) / 256, 256>>>(h1, head_w2, head_b2, pt,
                                                        BATCH, 256, EMB, 0);
    expand_kernel<<<(BATCH * 224 * 224 + 255) / 256, 256>>>(pt, out);
}